// round 17
// baseline (speedup 1.0000x reference)
#include <cuda_runtime.h>
#include <cstdint>

#define KIDS 64
#define NCANDS 16
#define BCH 8                    // int4 chunks per batch: 8 x 128 = 1024 px
#define SENTI 0x7FFFFFFF

// Single packed accumulator: bits[0:7)=arrive count, [7:13)=valid count,
// [13:64)=sum of per-instance losses in 2^30 fixed point (exact int adds =>
// deterministic across replays regardless of arrival order).
__device__ unsigned long long g_acc = 0ULL;   // reset by the winner each launch

// ---------------- compile-time threefry (host constexpr mirror) ----------------
constexpr uint32_t crotl(uint32_t v, int d) { return (v << d) | (v >> (32 - d)); }
constexpr unsigned long long ctf(uint32_t k0, uint32_t k1,
                                 uint32_t x0, uint32_t x1) {
    uint32_t k2 = k0 ^ k1 ^ 0x1BD11BDAu;
    x0 += k0; x1 += k1;
#define CR_(r) { x0 += x1; x1 = crotl(x1, (r)); x1 ^= x0; }
    CR_(13) CR_(15) CR_(26) CR_(6)   x0 += k1; x1 += k2 + 1u;
    CR_(17) CR_(29) CR_(16) CR_(24)  x0 += k2; x1 += k0 + 2u;
    CR_(13) CR_(15) CR_(26) CR_(6)   x0 += k0; x1 += k1 + 3u;
    CR_(17) CR_(29) CR_(16) CR_(24)  x0 += k1; x1 += k2 + 4u;
    CR_(13) CR_(15) CR_(26) CR_(6)   x0 += k2; x1 += k0 + 5u;
#undef CR_
    return ((unsigned long long)x0 << 32) | x1;
}
// child key of split(key(1)) — fully input-independent
constexpr unsigned long long KKC = ctf(0u, 1u, 0u, 1u);
#define KK0 ((uint32_t)(KKC >> 32))
#define KK1 ((uint32_t)KKC)

// ---------------- runtime threefry (device, bit-exact) ----------------
__device__ __forceinline__ uint32_t rotl32(uint32_t v, int d) {
    return __funnelshift_l(v, v, d);
}
__device__ __forceinline__ void tf2x32(uint32_t k0, uint32_t k1,
                                       uint32_t x0, uint32_t x1,
                                       uint32_t& o0, uint32_t& o1) {
    uint32_t k2 = k0 ^ k1 ^ 0x1BD11BDAu;
    x0 += k0; x1 += k1;
#define R_(r) { x0 += x1; x1 = rotl32(x1, (r)); x1 ^= x0; }
    R_(13) R_(15) R_(26) R_(6)   x0 += k1; x1 += k2 + 1u;
    R_(17) R_(29) R_(16) R_(24)  x0 += k2; x1 += k0 + 2u;
    R_(13) R_(15) R_(26) R_(6)   x0 += k0; x1 += k1 + 3u;
    R_(17) R_(29) R_(16) R_(24)  x0 += k1; x1 += k2 + 4u;
    R_(13) R_(15) R_(26) R_(6)   x0 += k2; x1 += k0 + 5u;
#undef R_
    o0 = x0; o1 = x1;
}

// Warp-uniform: fold the two smallest positions of id k in this 128-px chunk
// into (f, s, done). x = this lane's 4 consecutive ids. No atomics, no smem.
__device__ __forceinline__ void scan_chunk(int4 x, int k, int base,
                                           int& f, int& s, bool& done) {
    unsigned m = (x.x == k ? 1u : 0u) | (x.y == k ? 2u : 0u) |
                 (x.z == k ? 4u : 0u) | (x.w == k ? 8u : 0u);
    unsigned b = __ballot_sync(0xffffffffu, m != 0u);
    if (!b) return;
    int l1 = __ffs(b) - 1;
    unsigned m1 = __shfl_sync(0xffffffffu, m, l1);
    int pos1 = base + l1 * 4 + (__ffs(m1) - 1);
    int pos2 = -1;
    unsigned m1r = m1 & (m1 - 1);
    if (m1r) {
        pos2 = base + l1 * 4 + (__ffs(m1r) - 1);
    } else {
        unsigned b2 = b & (b - 1);
        if (b2) {
            int l2 = __ffs(b2) - 1;
            unsigned m2 = __shfl_sync(0xffffffffu, m, l2);
            pos2 = base + l2 * 4 + (__ffs(m2) - 1);
        }
    }
    if (f == SENTI) {
        f = pos1;
        if (pos2 >= 0) { s = pos2; done = true; }
    } else {
        s = pos1; done = true;
    }
}

__device__ __forceinline__ void load_batch(int4* v, const int* __restrict__ mask,
                                           int base, int HW, int lane) {
    #pragma unroll
    for (int c = 0; c < BCH; c++) {
        int p = base + c * 128 + lane * 4;
        if (p + 3 < HW) {
            v[c] = *reinterpret_cast<const int4*>(mask + p);
        } else {
            v[c] = make_int4(-1, -1, -1, -1);
            if (p     < HW) v[c].x = mask[p];
            if (p + 1 < HW) v[c].y = mask[p + 1];
            if (p + 2 < HW) v[c].z = mask[p + 2];
        }
    }
}

// One warp per block; block k owns id k end-to-end. No smem, no barriers.
__global__ void __launch_bounds__(32)
per_id_kernel(const float* __restrict__ sem, const int* __restrict__ mask,
              float* __restrict__ out, int HW, int BC) {
    int lane = threadIdx.x;
    int k = blockIdx.x;

    // ---- batch 0 of the scan: issued first, no dependencies ----
    int4 v[BCH];
    load_batch(v, mask, 0, HW, lane);

    // ---- candidates: threefry (ALU, overlaps loads), then the gather ----
    int cand = 0, candval = 0;
    if (lane < NCANDS) {
        uint32_t o0, o1;
        tf2x32(KK0, KK1, 0u, (uint32_t)(k * NCANDS + lane), o0, o1);
        cand = (int)((o0 ^ o1) % (uint32_t)HW);
        candval = __ldg(mask + cand);            // in flight...
    }

    // ---- ballot scan: two smallest positions of id k ----
    int f = SENTI, s = SENTI;
    bool done = false;
    int base = 0;
    while (true) {
        #pragma unroll
        for (int c = 0; c < BCH; c++)
            if (!done) scan_chunk(v[c], k, base + c * 128, f, s, done);
        base += BCH * 128;
        if (done || base >= HW) break;           // exact fallback: keep going
        load_batch(v, mask, base, HW, lane);
    }

    bool valid = (s != SENTI) && (k != 0);       // second exists <=> count >= 2
    int fi = min(f, HW - 1);
    int si = min(s, HW - 1);

    // ---- a/p gathers issued immediately (independent of the negative) ----
    float av[4], pv[4];
    #pragma unroll
    for (int i = 0; i < 4; i++) {                // covers BC <= 128 (BC = 76)
        int c = lane + i * 32;
        if (c < BC) {
            size_t off = (size_t)c * (size_t)HW;
            av[i] = __ldg(sem + off + fi);
            pv[i] = __ldg(sem + off + si);
        } else { av[i] = 0.f; pv[i] = 0.f; }
    }

    // ---- resolve the negative (candval has landed), then n gathers ----
    bool ok = (lane < NCANDS) && (candval != k);
    unsigned bal = __ballot_sync(0xffffffffu, ok) & 0xFFFFu;
    int neg = __shfl_sync(0xffffffffu, cand, bal ? (__ffs(bal) - 1) : 0);

    float dap = 0.f, dan = 0.f;
    #pragma unroll
    for (int i = 0; i < 4; i++) {
        int c = lane + i * 32;
        if (c < BC) {
            float n = __ldg(sem + (size_t)c * (size_t)HW + neg);
            float e1 = av[i] - pv[i] + 1e-6f;
            float e2 = av[i] - n    + 1e-6f;
            dap = fmaf(e1, e1, dap);
            dan = fmaf(e2, e2, dan);
        }
    }
    for (int c = lane + 128; c < BC; c += 32) {  // generic tail (unused here)
        size_t off = (size_t)c * (size_t)HW;
        float a  = __ldg(sem + off + fi);
        float p2 = __ldg(sem + off + si);
        float n  = __ldg(sem + off + neg);
        float e1 = a - p2 + 1e-6f;
        float e2 = a - n  + 1e-6f;
        dap = fmaf(e1, e1, dap);
        dan = fmaf(e2, e2, dan);
    }
    #pragma unroll
    for (int o = 16; o; o >>= 1) {
        dap += __shfl_down_sync(0xffffffffu, dap, o);
        dan += __shfl_down_sync(0xffffffffu, dan, o);
    }
    if (lane == 0) {
        float per = fmaxf(sqrtf(dap) - sqrtf(dan) + 1.0f, 0.0f);
        unsigned long long fx = valid
            ? (unsigned long long)((double)per * 1073741824.0 + 0.5) : 0ULL;
        unsigned long long add = (fx << 13) |
                                 (valid ? (1ULL << 7) : 0ULL) | 1ULL;
        unsigned long long old = atomicAdd(&g_acc, add);
        if ((old & 0x7FULL) == (unsigned long long)(KIDS - 1)) {
            unsigned long long full = old + add;   // exact packed total
            unsigned cnt = (unsigned)((full >> 7) & 0x3FULL);
            double tot = (double)(full >> 13) * (1.0 / 1073741824.0);
            out[0] = (cnt > 0) ? (float)(tot / (double)cnt) : 0.0f;
            g_acc = 0ULL;            // reset for the next graph replay
        }
    }
}

extern "C" void kernel_launch(void* const* d_in, const int* in_sizes, int n_in,
                              void* d_out, int out_size) {
    const float* sem  = (const float*)d_in[0];
    const int*   mask = (const int*)d_in[1];
    float*       out  = (float*)d_out;
    int HW = in_sizes[1];
    int BC = in_sizes[0] / HW;

    per_id_kernel<<<KIDS, 32>>>(sem, mask, out, HW, BC);
}